// round 11
// baseline (speedup 1.0000x reference)
#include <cuda_runtime.h>

#define BB   8
#define NN   128
#define COOR 3
#define FF   128
#define FILT 128

// Scratch: A' = x @ w1 + bv  and  C = x @ w2, each [B, N, COOR, FILT]
__device__ float g_A[BB * NN * COOR * FILT];
__device__ float g_C[BB * NN * COOR * FILT];

// ---- packed f32x2 helpers (phase 1 only) ----------------------------------
typedef unsigned long long ull;

union F2U {
    float2 f2;
    ull    u;
};

__device__ __forceinline__ ull fma2(ull a, ull b, ull c) {
    ull r;
    asm("fma.rn.f32x2 %0, %1, %2, %3;" : "=l"(r) : "l"(a), "l"(b), "l"(c));
    return r;
}
__device__ __forceinline__ ull pack2(float lo, float hi) {
    ull r;
    asm("mov.b64 %0, {%1, %2};" : "=l"(r) : "r"(__float_as_uint(lo)), "r"(__float_as_uint(hi)));
    return r;
}

// ---------------------------------------------------------------------------
// Phase 1 — R7 structure (best measured), pipeline deepened to DEPTH=16:
// at NAT clocks the effective L2 latency is ~400+cyc (262 was @LOCK), so
// the depth-8 cover (~500cyc incl. issue dilution) was marginal. 16 slots
// span ~1000cyc. 128 % 16 == 0 so slot indices stay compile-time.
// Grid (384, 2) = 768 blocks x 4 warps = 20.8 warps/SM.
// ---------------------------------------------------------------------------
__global__ __launch_bounds__(128) void phase1_kernel(
    const float* __restrict__ x,   // [3072, 128]
    const float* __restrict__ w,   // [256, 128]
    const float* __restrict__ bv)  // [128]
{
    constexpr int RT    = 8;             // rows per block
    constexpr int DEPTH = 16;            // w-prefetch pipeline depth
    const int r0   = blockIdx.x * RT;
    const int kh   = blockIdx.y * 64;    // k half
    const int warp = threadIdx.x >> 5;   // 0..3
    const int lane = threadIdx.x & 31;
    const int k    = kh + lane * 2;      // this thread's k-pair
    const int wr   = warp * 2;           // first of this warp's 2 rows

    __shared__ float xs[RT][FF];         // 4 KB

    {
        const float4* xin = reinterpret_cast<const float4*>(x + (size_t)r0 * FF);
        float4* xs4 = reinterpret_cast<float4*>(&xs[0][0]);
        #pragma unroll
        for (int t = threadIdx.x; t < RT * FF / 4; t += 128) xs4[t] = xin[t];
    }
    __syncthreads();

    ull acc[2][2];   // [row][A/C]
    {
        const float2 b2 = *reinterpret_cast<const float2*>(bv + k);
        const ull bp = pack2(b2.x, b2.y);
        acc[0][0] = bp; acc[0][1] = 0ull;
        acc[1][0] = bp; acc[1][1] = 0ull;
    }

    const float* w1base = w + k;
    const float* w2base = w + (size_t)FF * FILT + k;

    // Prime the depth-16 rotating pipeline.
    F2U W1[DEPTH], W2[DEPTH];
    #pragma unroll
    for (int d = 0; d < DEPTH; d++) {
        W1[d].f2 = *reinterpret_cast<const float2*>(w1base + (size_t)d * FILT);
        W2[d].f2 = *reinterpret_cast<const float2*>(w2base + (size_t)d * FILT);
    }

    #pragma unroll 16   // = DEPTH; 128 % 16 == 0 -> slot is compile-time
    for (int f = 0; f < FF; f++) {
        const int slot = f % DEPTH;

        const float xv0 = xs[wr + 0][f];
        const float xv1 = xs[wr + 1][f];
        const ull xp0 = pack2(xv0, xv0);
        const ull xp1 = pack2(xv1, xv1);

        const ull w1v = W1[slot].u;
        const ull w2v = W2[slot].u;

        acc[0][0] = fma2(xp0, w1v, acc[0][0]);
        acc[0][1] = fma2(xp0, w2v, acc[0][1]);
        acc[1][0] = fma2(xp1, w1v, acc[1][0]);
        acc[1][1] = fma2(xp1, w2v, acc[1][1]);

        // Refill this slot for iteration f + DEPTH.
        if (f + DEPTH < FF) {
            W1[slot].f2 = *reinterpret_cast<const float2*>(w1base + (size_t)(f + DEPTH) * FILT);
            W2[slot].f2 = *reinterpret_cast<const float2*>(w2base + (size_t)(f + DEPTH) * FILT);
        }
    }

    #pragma unroll
    for (int r = 0; r < 2; r++) {
        const size_t row = (size_t)(r0 + wr + r);
        F2U oa; oa.u = acc[r][0];
        F2U oc; oc.u = acc[r][1];
        *reinterpret_cast<float2*>(&g_A[row * FILT + k]) = oa.f2;
        *reinterpret_cast<float2*>(&g_C[row * FILT + k]) = oc.f2;
    }
}

// ---------------------------------------------------------------------------
// Phase 2: out[b,i,j,k] = sum_c (A'[b,i,c,k] + C[b,j,c,k]) * d[b,i,j,c]
// R4 skeleton (scalar FMA, padded dist smem, 1-ahead C prefetch) with
// TI=2 to CUT REGISTERS (~116 -> ~75): __launch_bounds__(256,3) gives
// 3 blocks/SM = 24 warps/SM (was 16) — occupancy was the invariant binder
// across 4 structural variants. Grid (64, 8) = 512 blocks (1.15 waves,
// ~+1us tail, paid for by 1.5x latency cover). C-reads double (50->100MB);
// L2 was at 40%, headroom exists.
// ---------------------------------------------------------------------------
__global__ __launch_bounds__(256, 3) void phase2_kernel(
    const float* __restrict__ dist,  // [B, N, N, COOR]
    float* __restrict__ out)         // [B, N, N, FILT]
{
    constexpr int TI = 2;
    const int b  = blockIdx.y;
    const int i0 = blockIdx.x * TI;
    const int tx = threadIdx.x;   // 0..31
    const int ty = threadIdx.y;   // 0..7
    const int tid = ty * 32 + tx;

    __shared__ float4 sd4[TI * NN];   // padded (d0,d1,d2,_) per (i,j): 4 KB

    // Load + pad distances slice d[b, i0:i0+2, :, :].
    {
        const float* dbase = dist + (size_t)(b * NN + i0) * NN * COOR;
        #pragma unroll
        for (int t = tid; t < TI * NN; t += 256) {
            const int e = t * COOR;
            sd4[t] = make_float4(dbase[e], dbase[e + 1], dbase[e + 2], 0.0f);
        }
    }

    // A' tile into registers: 2 i x 3 c x float4 = 24 regs.
    float4 Ar[TI][COOR];
    {
        const float4* A4 = reinterpret_cast<const float4*>(g_A);
        #pragma unroll
        for (int i = 0; i < TI; i++)
            #pragma unroll
            for (int c = 0; c < COOR; c++)
                Ar[i][c] = A4[((size_t)(b * NN + i0 + i) * COOR + c) * (FILT / 4) + tx];
    }
    __syncthreads();

    const float4* C4 = reinterpret_cast<const float4*>(g_C) +
                       (size_t)b * NN * COOR * (FILT / 4) + tx;
    float4* out4 = reinterpret_cast<float4*>(out) +
                   ((size_t)(b * NN + i0) * NN) * (FILT / 4) + tx;

    // Prime C pipeline with j = ty.
    float4 c0 = C4[(size_t)ty * COOR * (FILT / 4) + 0 * (FILT / 4)];
    float4 c1 = C4[(size_t)ty * COOR * (FILT / 4) + 1 * (FILT / 4)];
    float4 c2 = C4[(size_t)ty * COOR * (FILT / 4) + 2 * (FILT / 4)];

    #pragma unroll
    for (int it = 0; it < NN / 8; it++) {
        const int j = ty + it * 8;

        float4 n0, n1, n2;
        if (it + 1 < NN / 8) {
            const size_t nb = (size_t)(j + 8) * COOR * (FILT / 4);
            n0 = C4[nb + 0 * (FILT / 4)];
            n1 = C4[nb + 1 * (FILT / 4)];
            n2 = C4[nb + 2 * (FILT / 4)];
        }

        #pragma unroll
        for (int i = 0; i < TI; i++) {
            const float4 dv = sd4[i * NN + j];   // one LDS.128 broadcast
            const float d0 = dv.x, d1 = dv.y, d2 = dv.z;

            float4 o;
            o.x = fmaf(Ar[i][0].x + c0.x, d0,
                  fmaf(Ar[i][1].x + c1.x, d1, (Ar[i][2].x + c2.x) * d2));
            o.y = fmaf(Ar[i][0].y + c0.y, d0,
                  fmaf(Ar[i][1].y + c1.y, d1, (Ar[i][2].y + c2.y) * d2));
            o.z = fmaf(Ar[i][0].z + c0.z, d0,
                  fmaf(Ar[i][1].z + c1.z, d1, (Ar[i][2].z + c2.z) * d2));
            o.w = fmaf(Ar[i][0].w + c0.w, d0,
                  fmaf(Ar[i][1].w + c1.w, d1, (Ar[i][2].w + c2.w) * d2));

            out4[((size_t)i * NN + j) * (FILT / 4)] = o;
        }

        c0 = n0; c1 = n1; c2 = n2;
    }
}

extern "C" void kernel_launch(void* const* d_in, const int* in_sizes, int n_in,
                              void* d_out, int out_size)
{
    const float* x    = (const float*)d_in[0];  // vector_features [8,128,3,128]
    const float* dist = (const float*)d_in[1];  // distances       [8,128,128,3]
    const float* w    = (const float*)d_in[2];  // w_vs            [256,128]
    const float* bv   = (const float*)d_in[3];  // b_vs            [128]
    float* out = (float*)d_out;                 // [8,128,128,128]

    (void)in_sizes; (void)n_in; (void)out_size;

    phase1_kernel<<<dim3((BB * NN * COOR) / 8, 2), 128>>>(x, w, bv);
    phase2_kernel<<<dim3(NN / 2, BB), dim3(32, 8)>>>(dist, out);
}